// round 16
// baseline (speedup 1.0000x reference)
#include <cuda_runtime.h>
#include <cstdint>

#define NLV 16
#define TSIZE (1u << 19)
#define HMASK (TSIZE - 1u)
#define PRIME1 2654435761u
#define PRIME2 805459861u

#define BINRES 32
#define BINS 32768                    // 32^3 Morton bins
#define NSLOTS 2097152u               // BINS * 64
#define OVMAX 65536u

__device__ unsigned g_cnt[BINS];
__device__ unsigned g_over[1];
__device__ float4   g_xs[2097152];    // bucketed points, xyz + orig index in w (32MB)
__device__ float4   g_xso[65536];     // overflow (1MB)

// floor(16 * b^i), b = exp((ln512 - ln16)/15) evaluated in float32 (numpy chain)
__device__ const float g_res[NLV] = {16.f, 20.f, 25.f, 32.f, 40.f, 50.f, 64.f, 80.f,
                                     101.f, 128.f, 161.f, 203.f, 256.f, 322.f, 406.f, 512.f};

static __device__ __forceinline__ float2 lerp2(float2 a, float2 b, float w) {
    float u = 1.0f - w;
    return make_float2(a.x * u + b.x * w, a.y * u + b.y * w);
}

// 5-bit 3D Morton expand: b4..b0 -> bits 12,9,6,3,0
static __device__ __forceinline__ unsigned expand_bits5(unsigned v) {
    v &= 0x1Fu;
    v = (v | (v << 8)) & 0x100Fu;
    v = (v | (v << 4)) & 0x10C3u;
    v = (v | (v << 2)) & 0x1249u;
    return v;
}

static __device__ __forceinline__ unsigned point_bin(float x0, float x1, float x2,
                                                     float bm0, float bm1, float bm2,
                                                     float bM0, float bM1, float bM2) {
    float u0 = (fminf(fmaxf(x0, bm0), bM0) - bm0) / (bM0 - bm0);
    float u1 = (fminf(fmaxf(x1, bm1), bM1) - bm1) / (bM1 - bm1);
    float u2 = (fminf(fmaxf(x2, bm2), bM2) - bm2) / (bM2 - bm2);
    unsigned i0 = min((unsigned)(u0 * (float)BINRES), (unsigned)(BINRES - 1));
    unsigned i1 = min((unsigned)(u1 * (float)BINRES), (unsigned)(BINRES - 1));
    unsigned i2 = min((unsigned)(u2 * (float)BINRES), (unsigned)(BINRES - 1));
    return expand_bits5(i0) | (expand_bits5(i1) << 1) | (expand_bits5(i2) << 2);
}

static __device__ __forceinline__ void deposit(float q0, float q1, float q2,
                                               unsigned idx,
                                               float bm0, float bm1, float bm2,
                                               float bM0, float bM1, float bM2) {
    unsigned b = point_bin(q0, q1, q2, bm0, bm1, bm2, bM0, bM1, bM2);
    unsigned c = atomicAdd(&g_cnt[b], 1u);
    float4 v = make_float4(q0, q1, q2, __uint_as_float(idx));
    if (c < 64u) {
        g_xs[b * 64u + c] = v;
    } else {
        unsigned k = atomicAdd(&g_over[0], 1u);
        if (k < OVMAX) g_xso[k] = v;
    }
}

__global__ void __launch_bounds__(256)
scatter_kernel(const float* __restrict__ x,
               const float* __restrict__ bmin,
               const float* __restrict__ bmax, unsigned n) {
    unsigned t = blockIdx.x * blockDim.x + threadIdx.x;
    unsigned base = t * 8u;
    if (base >= n) return;
    float bm0 = __ldg(&bmin[0]), bm1 = __ldg(&bmin[1]), bm2 = __ldg(&bmin[2]);
    float bM0 = __ldg(&bmax[0]), bM1 = __ldg(&bmax[1]), bM2 = __ldg(&bmax[2]);
    if (base + 8 <= n) {
        const float4* x4 = (const float4*)x;
        float4 a[6];
#pragma unroll
        for (int q = 0; q < 6; q++)
            a[q] = __ldg(&x4[6 * (size_t)t + q]);
        const float* f = reinterpret_cast<const float*>(a);
#pragma unroll
        for (int k = 0; k < 8; k++)
            deposit(f[3 * k + 0], f[3 * k + 1], f[3 * k + 2], base + k,
                    bm0, bm1, bm2, bM0, bM1, bM2);
    } else {
        for (unsigned i = base; i < n; i++) {
            float q0 = __ldg(&x[3 * (size_t)i + 0]);
            float q1 = __ldg(&x[3 * (size_t)i + 1]);
            float q2 = __ldg(&x[3 * (size_t)i + 2]);
            deposit(q0, q1, q2, i, bm0, bm1, bm2, bM0, bM1, bM2);
        }
    }
}

// all 16 levels on bucketed (Morton-sorted) points; 2 levels pipelined per step
__global__ void __launch_bounds__(256)
hashenc_kernel(const float2* __restrict__ emb,   // [16][2^19] float2
               const float* __restrict__ lw,     // [16]
               const float* __restrict__ bmin,   // [3]
               const float* __restrict__ bmax,   // [3]
               float* __restrict__ out)          // [N, 32]
{
    // per-level constants, computed once per block
    __shared__ float sg0[NLV], sg1[NLV], sg2[NLV];       // grid components
    __shared__ float sr0[NLV], sr1[NLV], sr2[NLV];       // reciprocals (for cell index)
    __shared__ float sgate[NLV];
    if (threadIdx.x < NLV) {
        int l = threadIdx.x;
        float res = g_res[l];
        float bm0 = __ldg(&bmin[0]), bm1 = __ldg(&bmin[1]), bm2 = __ldg(&bmin[2]);
        float bM0 = __ldg(&bmax[0]), bM1 = __ldg(&bmax[1]), bM2 = __ldg(&bmax[2]);
        float g0 = (bM0 - bm0) / res;
        float g1 = (bM1 - bm1) / res;
        float g2 = (bM2 - bm2) / res;
        sg0[l] = g0; sg1[l] = g1; sg2[l] = g2;
        sr0[l] = 1.0f / g0; sr1[l] = 1.0f / g1; sr2[l] = 1.0f / g2;
        sgate[l] = 1.0f / (1.0f + expf(-lw[l]));
    }
    __syncthreads();

    unsigned j = blockIdx.x * blockDim.x + threadIdx.x;

    float4 xp;
    if (j < NSLOTS) {
        unsigned bin = j >> 6;
        unsigned slot = j & 63u;
        unsigned cnt = g_cnt[bin];
        if (slot >= min(cnt, 64u)) return;
        xp = g_xs[j];
    } else {
        unsigned k = j - NSLOTS;
        if (k >= min(g_over[0], OVMAX)) return;
        xp = g_xso[k];
    }

    unsigned p = __float_as_uint(xp.w);   // original point index (output row)
    float x0 = xp.x, x1 = xp.y, x2 = xp.z;

    float bm0 = __ldg(&bmin[0]), bm1 = __ldg(&bmin[1]), bm2 = __ldg(&bmin[2]);
    float bM0 = __ldg(&bmax[0]), bM1 = __ldg(&bmax[1]), bM2 = __ldg(&bmax[2]);

    float xc0 = fminf(fmaxf(x0, bm0), bM0);
    float xc1 = fminf(fmaxf(x1, bm1), bM1);
    float xc2 = fminf(fmaxf(x2, bm2), bM2);

    float4* orow = reinterpret_cast<float4*>(out + (size_t)p * (2 * NLV));

#pragma unroll
    for (int lp = 0; lp < NLV / 2; lp++) {
        const int la = 2 * lp;
        const int lb = 2 * lp + 1;

        // ---- addresses for BOTH levels ----
        unsigned ma[8], mb[8];
        float wxa, wya, wza, wxb, wyb, wzb;
        {
            float g0 = sg0[la], g1 = sg1[la], g2 = sg2[la];
            unsigned b0 = (unsigned)((xc0 - bm0) * sr0[la]);
            unsigned b1 = (unsigned)((xc1 - bm1) * sr1[la]);
            unsigned b2 = (unsigned)((xc2 - bm2) * sr2[la]);
            float v0 = (float)b0 * g0 + bm0;
            float v1 = (float)b1 * g1 + bm1;
            float v2 = (float)b2 * g2 + bm2;
            wxa = __fdividef(x0 - v0, (v0 + g0) - v0);
            wya = __fdividef(x1 - v1, (v1 + g1) - v1);
            wza = __fdividef(x2 - v2, (v2 + g2) - v2);
            unsigned hy0 = b1 * PRIME1;
            unsigned hz0 = b2 * PRIME2;
            unsigned m000 = (b0 ^ hy0 ^ hz0) & HMASK;
            unsigned dx = (b0 ^ (b0 + 1u)) & HMASK;
            unsigned dy = (hy0 ^ (hy0 + PRIME1)) & HMASK;
            unsigned dz = (hz0 ^ (hz0 + PRIME2)) & HMASK;
            ma[0] = m000;           ma[4] = m000 ^ dx;
            ma[2] = m000 ^ dy;      ma[6] = ma[4] ^ dy;
            ma[1] = m000 ^ dz;      ma[5] = ma[4] ^ dz;
            ma[3] = ma[2] ^ dz;     ma[7] = ma[6] ^ dz;
        }
        {
            float g0 = sg0[lb], g1 = sg1[lb], g2 = sg2[lb];
            unsigned b0 = (unsigned)((xc0 - bm0) * sr0[lb]);
            unsigned b1 = (unsigned)((xc1 - bm1) * sr1[lb]);
            unsigned b2 = (unsigned)((xc2 - bm2) * sr2[lb]);
            float v0 = (float)b0 * g0 + bm0;
            float v1 = (float)b1 * g1 + bm1;
            float v2 = (float)b2 * g2 + bm2;
            wxb = __fdividef(x0 - v0, (v0 + g0) - v0);
            wyb = __fdividef(x1 - v1, (v1 + g1) - v1);
            wzb = __fdividef(x2 - v2, (v2 + g2) - v2);
            unsigned hy0 = b1 * PRIME1;
            unsigned hz0 = b2 * PRIME2;
            unsigned m000 = (b0 ^ hy0 ^ hz0) & HMASK;
            unsigned dx = (b0 ^ (b0 + 1u)) & HMASK;
            unsigned dy = (hy0 ^ (hy0 + PRIME1)) & HMASK;
            unsigned dz = (hz0 ^ (hz0 + PRIME2)) & HMASK;
            mb[0] = m000;           mb[4] = m000 ^ dx;
            mb[2] = m000 ^ dy;      mb[6] = mb[4] ^ dy;
            mb[1] = m000 ^ dz;      mb[5] = mb[4] ^ dz;
            mb[3] = mb[2] ^ dz;     mb[7] = mb[6] ^ dz;
        }

        // ---- issue all 16 loads back-to-back (MLP 16) ----
        const float2* ta = emb + (size_t)la * TSIZE;
        const float2* tbp = emb + (size_t)lb * TSIZE;
        float2 ea[8], eb[8];
#pragma unroll
        for (int c = 0; c < 8; c++) ea[c] = __ldg(&ta[ma[c]]);
#pragma unroll
        for (int c = 0; c < 8; c++) eb[c] = __ldg(&tbp[mb[c]]);

        // ---- consume: both lerp trees (exact reference op order) ----
        float2 cxa0 = lerp2(ea[0], ea[4], wxa);
        float2 cxa1 = lerp2(ea[1], ea[5], wxa);
        float2 cxa2 = lerp2(ea[2], ea[6], wxa);
        float2 cxa3 = lerp2(ea[3], ea[7], wxa);
        float2 ca0 = lerp2(cxa0, cxa2, wya);
        float2 ca1 = lerp2(cxa1, cxa3, wya);
        float2 ca  = lerp2(ca0, ca1, wza);

        float2 cxb0 = lerp2(eb[0], eb[4], wxb);
        float2 cxb1 = lerp2(eb[1], eb[5], wxb);
        float2 cxb2 = lerp2(eb[2], eb[6], wxb);
        float2 cxb3 = lerp2(eb[3], eb[7], wxb);
        float2 cb0 = lerp2(cxb0, cxb2, wyb);
        float2 cb1 = lerp2(cxb1, cxb3, wyb);
        float2 cb  = lerp2(cb0, cb1, wzb);

        float ga = sgate[la];
        float gb = sgate[lb];
        orow[lp] = make_float4(ca.x * ga, ca.y * ga, cb.x * gb, cb.y * gb);
    }
}

extern "C" void kernel_launch(void* const* d_in, const int* in_sizes, int n_in,
                              void* d_out, int out_size) {
    const float*  x    = (const float*)d_in[0];
    const float2* emb  = (const float2*)d_in[1];
    const float*  lw   = (const float*)d_in[2];
    const float*  bmin = (const float*)d_in[3];
    const float*  bmax = (const float*)d_in[4];
    float* out = (float*)d_out;

    unsigned n = (unsigned)(in_sizes[0] / 3);
    unsigned t8 = (n + 7) / 8;

    void* cntPtr = nullptr;
    void* overPtr = nullptr;
    cudaGetSymbolAddress(&cntPtr, g_cnt);
    cudaGetSymbolAddress(&overPtr, g_over);
    cudaMemsetAsync(cntPtr, 0, BINS * sizeof(unsigned));
    cudaMemsetAsync(overPtr, 0, sizeof(unsigned));

    scatter_kernel<<<(t8 + 255) / 256, 256>>>(x, bmin, bmax, n);

    unsigned total = NSLOTS + OVMAX;
    hashenc_kernel<<<(total + 255) / 256, 256>>>(emb, lw, bmin, bmax, out);
}